// round 1
// baseline (speedup 1.0000x reference)
#include <cuda_runtime.h>
#include <cstdint>

#define N_BATCH 8192
#define EMB_D   128
#define NT      64                  // 8192/128 tiles per dim
#define NTILES  (NT*(NT+1)/2)       // 2080 upper-triangular tiles
#define CAP     (1<<21)             // 2M pair-entry capacity (expect ~524K)
#define FULLMASK 0xFFFFFFFFu
#define MARGIN 1.0f

__device__ unsigned g_negmin[N_BATCH];
__device__ float    g_sq[N_BATCH];
__device__ int      g_pairCount;
__device__ int      g_idxBuf[CAP];
__device__ float    g_distBuf[CAP];
__device__ float    g_total;
__device__ float    g_validCnt;

__device__ __forceinline__ float f_inf() { return __int_as_float(0x7f800000); }

// monotonic float<->uint encoding for atomicMin on floats
__device__ __forceinline__ unsigned encf(float f) {
    unsigned u = __float_as_uint(f);
    return (u & 0x80000000u) ? ~u : (u | 0x80000000u);
}
__device__ __forceinline__ float decf(unsigned u) {
    return (u & 0x80000000u) ? __uint_as_float(u & 0x7FFFFFFFu)
                             : __uint_as_float(~u);
}

__global__ void init_kernel() {
    int i = blockIdx.x * blockDim.x + threadIdx.x;
    if (i < N_BATCH) g_negmin[i] = 0xFFFFFFFFu;
    if (i == 0) { g_pairCount = 0; g_total = 0.f; g_validCnt = 0.f; }
}

// one warp per row: 32 lanes x float4 = 128 floats
__global__ void sqnorm_kernel(const float* __restrict__ E) {
    int row  = blockIdx.x * 8 + (threadIdx.x >> 5);
    int lane = threadIdx.x & 31;
    float4 v = reinterpret_cast<const float4*>(E + (size_t)row * EMB_D)[lane];
    float s = v.x*v.x + v.y*v.y + v.z*v.z + v.w*v.w;
    #pragma unroll
    for (int o = 16; o; o >>= 1) s += __shfl_xor_sync(FULLMASK, s, o);
    if (lane == 0) g_sq[row] = s;
}

// Main pass: 128x128 tile of the Gram matrix per CTA (upper triangle only).
// Epilogue: masked row/col mins -> atomicMin(neg_min), same-class i<j pairs
// appended to a global buffer with a single atomicAdd per CTA.
__global__ void __launch_bounds__(256, 2)
tri_kernel(const float* __restrict__ E, const int* __restrict__ labels) {
    __shared__ __align__(16) float As[16][132];
    __shared__ __align__(16) float Bs[16][132];
    __shared__ float cpart[16][128];
    __shared__ int   wsum[8];
    __shared__ int   sBase;

    // decode triangular tile index -> (bi, bj), bi <= bj
    int t = blockIdx.x;
    float ff = (float)(2 * NT + 1);
    int bi = (int)((ff - sqrtf(ff * ff - 8.0f * (float)t)) * 0.5f);
    while ((bi + 1) * NT - ((bi + 1) * bi) / 2 <= t) ++bi;
    while (bi * NT - (bi * (bi - 1)) / 2 > t) --bi;
    int bj = bi + (t - (bi * NT - (bi * (bi - 1)) / 2));

    const int rowBase = bi * 128, colBase = bj * 128;
    const int tid = threadIdx.x;
    const int tx = tid & 15, ty = tid >> 4;
    const int r = tid >> 1, half = tid & 1;

    float acc[8][8];
    #pragma unroll
    for (int p = 0; p < 8; p++)
        #pragma unroll
        for (int q = 0; q < 8; q++) acc[p][q] = 0.f;

    for (int kk = 0; kk < EMB_D; kk += 16) {
        const float* pa = E + (size_t)(rowBase + r) * EMB_D + kk + half * 8;
        const float* pb = E + (size_t)(colBase + r) * EMB_D + kk + half * 8;
        float4 a0 = *(const float4*)(pa);
        float4 a1 = *(const float4*)(pa + 4);
        float4 b0 = *(const float4*)(pb);
        float4 b1 = *(const float4*)(pb + 4);
        int kb = half * 8;
        As[kb+0][r]=a0.x; As[kb+1][r]=a0.y; As[kb+2][r]=a0.z; As[kb+3][r]=a0.w;
        As[kb+4][r]=a1.x; As[kb+5][r]=a1.y; As[kb+6][r]=a1.z; As[kb+7][r]=a1.w;
        Bs[kb+0][r]=b0.x; Bs[kb+1][r]=b0.y; Bs[kb+2][r]=b0.z; Bs[kb+3][r]=b0.w;
        Bs[kb+4][r]=b1.x; Bs[kb+5][r]=b1.y; Bs[kb+6][r]=b1.z; Bs[kb+7][r]=b1.w;
        __syncthreads();
        #pragma unroll
        for (int k = 0; k < 16; k++) {
            float4 va0 = *(const float4*)&As[k][ty * 8];
            float4 va1 = *(const float4*)&As[k][ty * 8 + 4];
            float4 vb0 = *(const float4*)&Bs[k][tx * 8];
            float4 vb1 = *(const float4*)&Bs[k][tx * 8 + 4];
            float a[8] = {va0.x,va0.y,va0.z,va0.w,va1.x,va1.y,va1.z,va1.w};
            float b[8] = {vb0.x,vb0.y,vb0.z,vb0.w,vb1.x,vb1.y,vb1.z,vb1.w};
            #pragma unroll
            for (int p = 0; p < 8; p++)
                #pragma unroll
                for (int q = 0; q < 8; q++)
                    acc[p][q] = fmaf(a[p], b[q], acc[p][q]);
        }
        __syncthreads();
    }

    // ---- epilogue ----
    int lr[8], lc[8]; float sr[8], sc[8];
    #pragma unroll
    for (int p = 0; p < 8; p++) {
        int gi = rowBase + ty * 8 + p;
        lr[p] = labels[gi]; sr[p] = g_sq[gi];
    }
    #pragma unroll
    for (int q = 0; q < 8; q++) {
        int gj = colBase + tx * 8 + q;
        lc[q] = labels[gj]; sc[q] = g_sq[gj];
    }

    float rmin[8], cminq[8];
    #pragma unroll
    for (int p = 0; p < 8; p++) rmin[p] = f_inf();
    #pragma unroll
    for (int q = 0; q < 8; q++) cminq[q] = f_inf();

    int cnt = 0;
    #pragma unroll
    for (int p = 0; p < 8; p++) {
        #pragma unroll
        for (int q = 0; q < 8; q++) {
            float d = sr[p] + sc[q] - 2.0f * acc[p][q];
            bool same = (lr[p] == lc[q]);
            float m = same ? f_inf() : d;
            rmin[p]  = fminf(rmin[p], m);
            cminq[q] = fminf(cminq[q], m);
            int gi = rowBase + ty * 8 + p, gj = colBase + tx * 8 + q;
            if (same && gi < gj) cnt++;
        }
    }

    // row-min reduce across tx (16 lanes within warp half)
    #pragma unroll
    for (int o = 1; o < 16; o <<= 1)
        #pragma unroll
        for (int p = 0; p < 8; p++)
            rmin[p] = fminf(rmin[p], __shfl_xor_sync(FULLMASK, rmin[p], o));
    if (tx == 0) {
        #pragma unroll
        for (int p = 0; p < 8; p++)
            atomicMin(&g_negmin[rowBase + ty * 8 + p], encf(rmin[p]));
    }

    // col-min partials -> shared -> reduce over 16 ty groups
    #pragma unroll
    for (int q = 0; q < 8; q++) cpart[ty][tx * 8 + q] = cminq[q];
    __syncthreads();
    if (tid < 128) {
        float m = f_inf();
        #pragma unroll
        for (int u = 0; u < 16; u++) m = fminf(m, cpart[u][tid]);
        atomicMin(&g_negmin[colBase + tid], encf(m));
    }

    // ---- same-class i<j pair append (block scan + one atomicAdd/CTA) ----
    int lane = tid & 31, w = tid >> 5;
    int inc = cnt;
    #pragma unroll
    for (int o = 1; o < 32; o <<= 1) {
        int n = __shfl_up_sync(FULLMASK, inc, o);
        if (lane >= o) inc += n;
    }
    if (lane == 31) wsum[w] = inc;
    __syncthreads();
    if (tid == 0) {
        int run = 0;
        #pragma unroll
        for (int u = 0; u < 8; u++) { int v = wsum[u]; wsum[u] = run; run += v; }
        sBase = atomicAdd(&g_pairCount, run);
    }
    __syncthreads();
    int off = sBase + wsum[w] + inc - cnt;
    #pragma unroll
    for (int p = 0; p < 8; p++) {
        #pragma unroll
        for (int q = 0; q < 8; q++) {
            int gi = rowBase + ty * 8 + p, gj = colBase + tx * 8 + q;
            if (lr[p] == lc[q] && gi < gj) {
                if (off < CAP) {
                    g_idxBuf[off]  = gi;
                    g_distBuf[off] = sr[p] + sc[q] - 2.0f * acc[p][q];
                }
                off++;
            }
        }
    }
}

__global__ void finalize_kernel() {
    int K = g_pairCount; if (K > CAP) K = CAP;
    float ls = 0.f, lcnt = 0.f;
    for (int e = blockIdx.x * blockDim.x + threadIdx.x; e < K;
         e += gridDim.x * blockDim.x) {
        int   i  = g_idxBuf[e];
        float d  = g_distBuf[e];
        float nm = decf(g_negmin[i]);
        float v  = d - nm + MARGIN;
        if (v > 0.f) { ls += v; lcnt += 1.f; }
    }
    #pragma unroll
    for (int o = 16; o; o >>= 1) {
        ls   += __shfl_xor_sync(FULLMASK, ls, o);
        lcnt += __shfl_xor_sync(FULLMASK, lcnt, o);
    }
    __shared__ float ss[8], scnt[8];
    int lane = threadIdx.x & 31, w = threadIdx.x >> 5;
    if (lane == 0) { ss[w] = ls; scnt[w] = lcnt; }
    __syncthreads();
    if (threadIdx.x == 0) {
        float a = 0.f, b = 0.f;
        #pragma unroll
        for (int u = 0; u < 8; u++) { a += ss[u]; b += scnt[u]; }
        atomicAdd(&g_total, a);
        atomicAdd(&g_validCnt, b);
    }
}

__global__ void out_kernel(float* __restrict__ out) {
    out[0] = g_total / fmaxf(g_validCnt, 1.0f);
}

extern "C" void kernel_launch(void* const* d_in, const int* in_sizes, int n_in,
                              void* d_out, int out_size) {
    const float* emb    = (const float*)d_in[0];
    const int*   labels = (const int*)d_in[1];
    float*       out    = (float*)d_out;

    init_kernel<<<(N_BATCH + 255) / 256, 256>>>();
    sqnorm_kernel<<<N_BATCH / 8, 256>>>(emb);
    tri_kernel<<<NTILES, 256>>>(emb, labels);
    finalize_kernel<<<256, 256>>>();
    out_kernel<<<1, 1>>>(out);
}

// round 6
// speedup vs baseline: 1.1085x; 1.1085x over previous
#include <cuda_runtime.h>
#include <cuda_bf16.h>
#include <cstdint>

#define N_BATCH 8192
#define EMB_D   128
#define NT      64
#define NTILES  (NT*(NT+1)/2)       // 2080
#define CAP     (1<<21)
#define FULLMASK 0xFFFFFFFFu
#define MARGIN 1.0f

// SMEM tile: 128 rows x 136 bf16 (272B stride, 17 x 16B chunks -> conflict-free ldmatrix)
#define TROW_B   272u
#define TILE_B   (128u * TROW_B)     // 34816
#define OFF_WSUM 0u
#define OFF_SBASE 32u
#define OFF_LBLA 64u
#define OFF_LBLB 576u
#define OFF_SQA  1088u
#define OFF_SQB  1600u
#define OFF_TILE 4096u
#define AHI_OFF  (OFF_TILE)
#define ALO_OFF  (AHI_OFF + TILE_B)
#define BHI_OFF  (ALO_OFF + TILE_B)
#define BLO_OFF  (BHI_OFF + TILE_B)
#define OFF_DIST (OFF_TILE)          // dist[128][130] fp32 reuses tile region (66KB < 139KB)
#define SMEM_DYN (BLO_OFF + TILE_B)  // 143360

__device__ unsigned g_negmin[N_BATCH];
__device__ float    g_sq[N_BATCH];
__device__ int      g_pairCount;
__device__ int      g_idxBuf[CAP];
__device__ float    g_distBuf[CAP];
__device__ float    g_total;
__device__ float    g_validCnt;
__device__ __nv_bfloat16 g_Ehi[N_BATCH * EMB_D];
__device__ __nv_bfloat16 g_Elo[N_BATCH * EMB_D];

__device__ __forceinline__ float f_inf() { return __int_as_float(0x7f800000); }
__device__ __forceinline__ unsigned encf(float f) {
    unsigned u = __float_as_uint(f);
    return (u & 0x80000000u) ? ~u : (u | 0x80000000u);
}
__device__ __forceinline__ float decf(unsigned u) {
    return (u & 0x80000000u) ? __uint_as_float(u & 0x7FFFFFFFu)
                             : __uint_as_float(~u);
}
__device__ __forceinline__ uint32_t smem_u32(const void* p) {
    uint32_t a;
    asm("{ .reg .u64 t; cvta.to.shared.u64 t, %1; cvt.u32.u64 %0, t; }"
        : "=r"(a) : "l"(p));
    return a;
}
__device__ __forceinline__ void ldsm_x4(uint32_t* r, uint32_t addr) {
    asm volatile("ldmatrix.sync.aligned.m8n8.x4.shared.b16 {%0,%1,%2,%3}, [%4];"
                 : "=r"(r[0]), "=r"(r[1]), "=r"(r[2]), "=r"(r[3]) : "r"(addr));
}
__device__ __forceinline__ void mma16816(float* c, const uint32_t* a,
                                         uint32_t b0, uint32_t b1) {
    asm volatile(
        "mma.sync.aligned.m16n8k16.row.col.f32.bf16.bf16.f32 "
        "{%0,%1,%2,%3}, {%4,%5,%6,%7}, {%8,%9}, {%0,%1,%2,%3};"
        : "+f"(c[0]), "+f"(c[1]), "+f"(c[2]), "+f"(c[3])
        : "r"(a[0]), "r"(a[1]), "r"(a[2]), "r"(a[3]), "r"(b0), "r"(b1));
}

// ---------- prep: fp32 -> bf16 hi/lo, row sq-norms, init state ----------
__global__ void prep_kernel(const float* __restrict__ E) {
    int gtid = blockIdx.x * 256 + threadIdx.x;          // 131072 threads, 8 floats each
    const float4* p = reinterpret_cast<const float4*>(E) + (size_t)gtid * 2;
    float4 v0 = p[0], v1 = p[1];
    float x[8] = {v0.x, v0.y, v0.z, v0.w, v1.x, v1.y, v1.z, v1.w};
    uint32_t h[8], l[8];
    float s = 0.f;
    #pragma unroll
    for (int k = 0; k < 8; k++) {
        __nv_bfloat16 hb = __float2bfloat16(x[k]);
        __nv_bfloat16 lb = __float2bfloat16(x[k] - __bfloat162float(hb));
        h[k] = (uint32_t)__bfloat16_as_ushort(hb);
        l[k] = (uint32_t)__bfloat16_as_ushort(lb);
        s = fmaf(x[k], x[k], s);
    }
    uint4 uh = make_uint4(h[0]|(h[1]<<16), h[2]|(h[3]<<16), h[4]|(h[5]<<16), h[6]|(h[7]<<16));
    uint4 ul = make_uint4(l[0]|(l[1]<<16), l[2]|(l[3]<<16), l[4]|(l[5]<<16), l[6]|(l[7]<<16));
    reinterpret_cast<uint4*>(g_Ehi)[gtid] = uh;
    reinterpret_cast<uint4*>(g_Elo)[gtid] = ul;
    #pragma unroll
    for (int o = 1; o < 16; o <<= 1) s += __shfl_xor_sync(FULLMASK, s, o);
    if ((threadIdx.x & 15) == 0) g_sq[gtid >> 4] = s;
    if (gtid < N_BATCH) g_negmin[gtid] = 0xFFFFFFFFu;
    if (gtid == 0) { g_pairCount = 0; g_total = 0.f; g_validCnt = 0.f; }
}

// ---------- main: HMMA bf16-split Gram tile + fused epilogue ----------
__global__ void __launch_bounds__(256, 1)
tri_kernel(const int* __restrict__ labels) {
    extern __shared__ char base[];
    const uint32_t sb = smem_u32(base);

    int*   lblA = (int*)(base + OFF_LBLA);
    int*   lblB = (int*)(base + OFF_LBLB);
    float* sqA  = (float*)(base + OFF_SQA);
    float* sqB  = (float*)(base + OFF_SQB);
    int*   wsum = (int*)(base + OFF_WSUM);
    int*   sBse = (int*)(base + OFF_SBASE);
    float* dist = (float*)(base + OFF_DIST);

    // triangular decode
    int t = blockIdx.x;
    float ff = (float)(2 * NT + 1);
    int bi = (int)((ff - sqrtf(ff * ff - 8.0f * (float)t)) * 0.5f);
    while ((bi + 1) * NT - ((bi + 1) * bi) / 2 <= t) ++bi;
    while (bi * NT - (bi * (bi - 1)) / 2 > t) --bi;
    int bj = bi + (t - (bi * NT - (bi * (bi - 1)) / 2));
    const int rowBase = bi * 128, colBase = bj * 128;

    const int tid  = threadIdx.x;
    const int lane = tid & 31;
    const int wid  = tid >> 5;

    if (tid < 128) { lblA[tid] = labels[rowBase + tid]; sqA[tid] = g_sq[rowBase + tid]; }
    else { int u = tid - 128; lblB[u] = labels[colBase + u]; sqB[u] = g_sq[colBase + u]; }

    // copy bf16 hi/lo tiles into padded SMEM (half row per thread = 128B = 8x16B)
    {
        int row = tid >> 1, h = tid & 1;
        const uint4* sAh = (const uint4*)(g_Ehi + (size_t)(rowBase + row) * EMB_D + h * 64);
        const uint4* sAl = (const uint4*)(g_Elo + (size_t)(rowBase + row) * EMB_D + h * 64);
        const uint4* sBh = (const uint4*)(g_Ehi + (size_t)(colBase + row) * EMB_D + h * 64);
        const uint4* sBl = (const uint4*)(g_Elo + (size_t)(colBase + row) * EMB_D + h * 64);
        uint32_t dst = row * TROW_B + h * 128u;
        #pragma unroll
        for (int c = 0; c < 8; c++) {
            *(uint4*)(base + AHI_OFF + dst + c * 16) = sAh[c];
            *(uint4*)(base + ALO_OFF + dst + c * 16) = sAl[c];
            *(uint4*)(base + BHI_OFF + dst + c * 16) = sBh[c];
            *(uint4*)(base + BLO_OFF + dst + c * 16) = sBl[c];
        }
    }
    __syncthreads();

    // warp tile: 32 rows x 64 cols (warpM 0..3, warpN 0..1)
    const int warpM = wid & 3, warpN = wid >> 2;
    const int rowW = warpM * 32, colW = warpN * 64;

    float acc[2][8][4];
    #pragma unroll
    for (int m = 0; m < 2; m++)
        #pragma unroll
        for (int n = 0; n < 8; n++)
            #pragma unroll
            for (int v = 0; v < 4; v++) acc[m][n][v] = 0.f;

    // lane -> ldmatrix source addresses (byte offsets within a tile)
    const uint32_t aLaneOff = (uint32_t)(rowW + (lane & 15)) * TROW_B + ((lane >> 4) << 4);
    const uint32_t bLaneOff = (uint32_t)(colW + (lane & 7) + ((lane >> 4) & 1) * 8) * TROW_B
                            + (((lane >> 3) & 1) << 4);

    const uint32_t aTiles[3] = { sb + AHI_OFF, sb + AHI_OFF, sb + ALO_OFF };
    const uint32_t bTiles[3] = { sb + BHI_OFF, sb + BLO_OFF, sb + BHI_OFF };

    #pragma unroll
    for (int pass = 0; pass < 3; pass++) {
        const uint32_t aBase = aTiles[pass] + aLaneOff;
        const uint32_t bBase = bTiles[pass] + bLaneOff;
        #pragma unroll
        for (int k = 0; k < 8; k++) {
            const uint32_t kb = (uint32_t)k * 32u;
            uint32_t af[2][4];
            ldsm_x4(af[0], aBase + kb);
            ldsm_x4(af[1], aBase + 16u * TROW_B + kb);
            #pragma unroll
            for (int nb = 0; nb < 4; nb++) {
                uint32_t bf[4];
                ldsm_x4(bf, bBase + (uint32_t)nb * 16u * TROW_B + kb);
                #pragma unroll
                for (int m = 0; m < 2; m++) {
                    mma16816(acc[m][2 * nb],     af[m], bf[0], bf[1]);
                    mma16816(acc[m][2 * nb + 1], af[m], bf[2], bf[3]);
                }
            }
        }
    }

    // write dist = sqA + sqB - 2*acc to SMEM (reuses tile region) -- all warps done reading tiles
    __syncthreads();
    #pragma unroll
    for (int m = 0; m < 2; m++) {
        int gm0 = rowW + m * 16 + (lane >> 2);
        float s0 = sqA[gm0], s1 = sqA[gm0 + 8];
        #pragma unroll
        for (int n = 0; n < 8; n++) {
            int gn = colW + n * 8 + 2 * (lane & 3);
            float t0 = sqB[gn], t1 = sqB[gn + 1];
            float2 r0 = make_float2(fmaf(-2.f, acc[m][n][0], s0 + t0),
                                    fmaf(-2.f, acc[m][n][1], s0 + t1));
            float2 r1 = make_float2(fmaf(-2.f, acc[m][n][2], s1 + t0),
                                    fmaf(-2.f, acc[m][n][3], s1 + t1));
            *(float2*)(dist + gm0 * 130 + gn)       = r0;
            *(float2*)(dist + (gm0 + 8) * 130 + gn) = r1;
        }
    }
    __syncthreads();

    // phase A: row-mins (threads 0-127, one row each)
    if (tid < 128) {
        int i = tid, la = lblA[i];
        const float* dr = dist + i * 130;
        float rmin = f_inf();
        #pragma unroll 4
        for (int j = 0; j < 128; j++)
            if (la != lblB[j]) rmin = fminf(rmin, dr[j]);
        atomicMin(&g_negmin[rowBase + i], encf(rmin));
    } else {
        // phase B: col-mins (threads 128-255, one column each)
        int j = tid - 128, lb = lblB[j];
        float m = f_inf();
        #pragma unroll 4
        for (int i = 0; i < 128; i++)
            if (lblA[i] != lb) m = fminf(m, dist[i * 130 + j]);
        atomicMin(&g_negmin[colBase + j], encf(m));
    }

    // phase C: same-class i<j pair append (half row per thread)
    {
        int i = tid >> 1, h = tid & 1, j0 = h * 64;
        int la = lblA[i], gi = rowBase + i;
        int cnt = 0;
        #pragma unroll 8
        for (int jj = 0; jj < 64; jj++) {
            int j = j0 + jj;
            if (la == lblB[j] && gi < colBase + j) cnt++;
        }
        int w = tid >> 5;
        int inc = cnt;
        #pragma unroll
        for (int o = 1; o < 32; o <<= 1) {
            int n = __shfl_up_sync(FULLMASK, inc, o);
            if (lane >= o) inc += n;
        }
        if (lane == 31) wsum[w] = inc;
        __syncthreads();
        if (tid == 0) {
            int run = 0;
            #pragma unroll
            for (int u = 0; u < 8; u++) { int v = wsum[u]; wsum[u] = run; run += v; }
            *sBse = atomicAdd(&g_pairCount, run);
        }
        __syncthreads();
        int off = *sBse + wsum[w] + inc - cnt;
        for (int jj = 0; jj < 64; jj++) {
            int j = j0 + jj;
            if (la == lblB[j] && gi < colBase + j) {
                if (off < CAP) {
                    g_idxBuf[off]  = gi;
                    g_distBuf[off] = dist[i * 130 + j];
                }
                off++;
            }
        }
    }
}

__global__ void finalize_kernel() {
    int K = g_pairCount; if (K > CAP) K = CAP;
    float ls = 0.f, lcnt = 0.f;
    for (int e = blockIdx.x * blockDim.x + threadIdx.x; e < K;
         e += gridDim.x * blockDim.x) {
        int   i  = g_idxBuf[e];
        float d  = g_distBuf[e];
        float nm = decf(g_negmin[i]);
        float v  = d - nm + MARGIN;
        if (v > 0.f) { ls += v; lcnt += 1.f; }
    }
    #pragma unroll
    for (int o = 16; o; o >>= 1) {
        ls   += __shfl_xor_sync(FULLMASK, ls, o);
        lcnt += __shfl_xor_sync(FULLMASK, lcnt, o);
    }
    __shared__ float ss[8], scnt[8];
    int lane = threadIdx.x & 31, w = threadIdx.x >> 5;
    if (lane == 0) { ss[w] = ls; scnt[w] = lcnt; }
    __syncthreads();
    if (threadIdx.x == 0) {
        float a = 0.f, b = 0.f;
        #pragma unroll
        for (int u = 0; u < 8; u++) { a += ss[u]; b += scnt[u]; }
        atomicAdd(&g_total, a);
        atomicAdd(&g_validCnt, b);
    }
}

__global__ void out_kernel(float* __restrict__ out) {
    out[0] = g_total / fmaxf(g_validCnt, 1.0f);
}

extern "C" void kernel_launch(void* const* d_in, const int* in_sizes, int n_in,
                              void* d_out, int out_size) {
    const float* emb    = (const float*)d_in[0];
    const int*   labels = (const int*)d_in[1];
    float*       out    = (float*)d_out;

    cudaFuncSetAttribute(tri_kernel, cudaFuncAttributeMaxDynamicSharedMemorySize, SMEM_DYN);

    prep_kernel<<<(N_BATCH * EMB_D / 8) / 256, 256>>>(emb);
    tri_kernel<<<NTILES, 256, SMEM_DYN>>>(labels);
    finalize_kernel<<<256, 256>>>();
    out_kernel<<<1, 1>>>(out);
}